// round 15
// baseline (speedup 1.0000x reference)
#include <cuda_runtime.h>
#include <math.h>

// ---------------- problem constants ----------------
constexpr int NNODES = 10000;
constexpr int HDIM   = 64;
constexpr int NHEADS = 4;
constexpr int OCDIM  = 16;
constexpr int NE     = 160000;
constexpr int NG     = 2;             // only graphs 3 and 7 are used
constexpr int CAP    = 128;           // per-node edge-list capacity (deg ~ Poisson(16))

#define FULLMASK 0xffffffffu
__device__ __forceinline__ float MAXNORM() { return 9.96f; }  // (1-4e-3)/0.1
#define EPSF   1e-15f
#define CLIPT  (1.0f - 1e-7f)

// ---------------- scratch (no allocations allowed) ----------------
__device__ __align__(16) float    g_xt[NNODES * HDIM];
__device__ __align__(16) float    g_ai[NNODES * NHEADS];
__device__ __align__(16) float    g_aj[NNODES * NHEADS];
__device__               int      g_cnt[NG * NNODES];
__device__ __align__(16) int      g_edst[NG * NNODES * CAP];
__device__ __align__(16) float    g_ne[NG * NNODES * OCDIM];
__device__               float    g_nen[NG * NNODES];    // ‖g_ne row‖ (>=EPS)
__device__               float    g_hb[2 * HDIM];

// ---------------- helpers ----------------
__device__ __forceinline__ float wsum(float v) {
#pragma unroll
    for (int o = 16; o; o >>= 1) v += __shfl_xor_sync(FULLMASK, v, o);
    return v;
}
__device__ __forceinline__ float qsum(float v) {
    v += __shfl_xor_sync(FULLMASK, v, 1, 4);
    v += __shfl_xor_sync(FULLMASK, v, 2, 4);
    return v;
}
__device__ __forceinline__ float qmax(float v) {
    v = fmaxf(v, __shfl_xor_sync(FULLMASK, v, 1, 4));
    v = fmaxf(v, __shfl_xor_sync(FULLMASK, v, 2, 4));
    return v;
}

// ---------------- fused prep: zero counters + per-node xt/att dots + hb ----------------
__global__ void k_prep(const float* __restrict__ emb,
                       const float* __restrict__ atti,
                       const float* __restrict__ attj,
                       const float* __restrict__ b1,
                       const float* __restrict__ b2) {
    int gid = blockIdx.x * blockDim.x + threadIdx.x;
    if (gid < NG * NNODES) g_cnt[gid] = 0;

    int w = threadIdx.x >> 5, lane = threadIdx.x & 31;

    if (blockIdx.x == 1250) {
        if (w < 2) {
            const float* b = w ? b2 : b1;
            float u0 = b[lane], u1 = b[lane + 32];
            float raw = sqrtf(wsum(u0 * u0 + u1 * u1));
            float n1 = fmaxf(raw, EPSF);
            float f = tanhf(0.1f * n1) / (0.1f * n1);
            float a = f * u0, c = f * u1;
            float na = f * raw;
            float nac = fmaxf(na, EPSF);
            if (nac > MAXNORM()) { float s = MAXNORM() / nac; a *= s; c *= s; }
            g_hb[w * 64 + lane] = a;
            g_hb[w * 64 + lane + 32] = c;
        }
        return;
    }

    __shared__ float sx[8][64];
    int n = blockIdx.x * 8 + w;
    if (n >= NNODES) return;
    const float* er = emb + n * 64;
    float u0 = er[lane], u1 = er[lane + 32];
    float raw = sqrtf(wsum(u0 * u0 + u1 * u1));
    float n1 = fmaxf(raw, EPSF);
    float f = tanhf(0.1f * n1) / (0.1f * n1);
    float a = f * u0, b = f * u1;
    float na = f * raw;
    float nac = fmaxf(na, EPSF);
    float ps = (nac > MAXNORM()) ? MAXNORM() / nac : 1.f;
    a *= ps; b *= ps;
    float n3 = fmaxf(na * ps, EPSF);
    float t = fminf(0.1f * n3, CLIPT);
    float lf = atanhf(t) / (0.1f * n3);
    a *= lf; b *= lf;
    g_xt[n * 64 + lane] = a;
    g_xt[n * 64 + lane + 32] = b;
    sx[w][lane] = a; sx[w][lane + 32] = b;
    __syncwarp();
    if (lane < 8) {
        int h = lane & 3;
        const float* att = (lane < 4) ? atti : attj;
        float s = 0.f;
#pragma unroll
        for (int k = 0; k < 16; k++) s += sx[w][h * 16 + k] * att[h * 16 + k];
        if (lane < 4) g_ai[n * 4 + h] = s; else g_aj[n * 4 + h] = s;
    }
}

// ---------------- bin edges by src (CSR, 4 edges per thread for MLP) ----------------
__global__ void k_scatter(const int* __restrict__ ei) {
    constexpr int Q = NE / 4;
    int t = blockIdx.x * blockDim.x + threadIdx.x;
    if (t >= NG * Q) return;
    int gi = t / Q, q = t - gi * Q;
    int g = 3 + 4 * gi;
    const int4 s4 = ((const int4*)(ei + (size_t)g * 2 * NE))[q];
    const int4 d4 = ((const int4*)(ei + (size_t)g * 2 * NE + NE))[q];
    int nb = gi * NNODES;
    int p0 = atomicAdd(&g_cnt[nb + s4.x], 1);
    int p1 = atomicAdd(&g_cnt[nb + s4.y], 1);
    int p2 = atomicAdd(&g_cnt[nb + s4.z], 1);
    int p3 = atomicAdd(&g_cnt[nb + s4.w], 1);
    if (p0 < CAP) g_edst[(nb + s4.x) * CAP + p0] = d4.x;
    if (p1 < CAP) g_edst[(nb + s4.y) * CAP + p1] = d4.y;
    if (p2 < CAP) g_edst[(nb + s4.z) * CAP + p2] = d4.z;
    if (p3 < CAP) g_edst[(nb + s4.w) * CAP + p3] = d4.w;
}

// ---------------- per-node gather: parallel exp phase + tight FMA phase ----------------
__global__ void k_gather() {
    __shared__ float sE[8][32 * 4];
    __shared__ int   sD[8][32];
    int w = threadIdx.x >> 5, lane = threadIdx.x & 31;
    int wid = blockIdx.x * 8 + w;
    if (wid >= NG * NNODES) return;
    int gi = wid / NNODES, nsrc = wid - gi * NNODES;

    float4 ai4 = *(const float4*)(g_ai + nsrc * 4);
    int h1 = lane >> 4, h2 = h1 + 2;

    int deg = min(g_cnt[gi * NNODES + nsrc], CAP);
    const int* lst = g_edst + (gi * NNODES + nsrc) * CAP;
    int total = deg + 1;   // + self loop

    float acc1 = 0.f, acc2 = 0.f;
    float s0 = 0.f, s1a = 0.f, s2a = 0.f, s3a = 0.f;

    for (int base = 0; base < total; base += 32) {
        int idx = base + lane;
        int dl = (idx < deg) ? lst[idx] : nsrc;
        float4 ev = {0.f, 0.f, 0.f, 0.f};
        if (idx < total) {
            float4 aj = *(const float4*)(g_aj + dl * 4);
            float a0 = ai4.x + aj.x; a0 = a0 >= 0.f ? a0 : 0.2f * a0;
            float a1 = ai4.y + aj.y; a1 = a1 >= 0.f ? a1 : 0.2f * a1;
            float a2 = ai4.z + aj.z; a2 = a2 >= 0.f ? a2 : 0.2f * a2;
            float a3 = ai4.w + aj.w; a3 = a3 >= 0.f ? a3 : 0.2f * a3;
            ev.x = __expf(a0); ev.y = __expf(a1);
            ev.z = __expf(a2); ev.w = __expf(a3);
            s0 += ev.x; s1a += ev.y; s2a += ev.z; s3a += ev.w;
        }
        sD[w][lane] = dl;
        *(float4*)(&sE[w][lane * 4]) = ev;
        __syncwarp();
        int m = min(32, total - base);
#pragma unroll 4
        for (int j = 0; j < m; j++) {
            int d = sD[w][j];
            float e1 = sE[w][j * 4 + h1];
            float e2 = sE[w][j * 4 + h2];
            acc1 = fmaf(e1, g_xt[d * 64 + lane], acc1);
            acc2 = fmaf(e2, g_xt[d * 64 + lane + 32], acc2);
        }
        __syncwarp();
    }
    s0 = wsum(s0); s1a = wsum(s1a); s2a = wsum(s2a); s3a = wsum(s3a);
    float sh1 = h1 ? s1a : s0;
    float sh2 = h1 ? s3a : s2a;
    float v = acc1 / sh1 + acc2 / sh2;
    v += __shfl_xor_sync(FULLMASK, v, 16);
    float x = (lane < 16) ? v * 0.25f : 0.f;

    float raw = sqrtf(wsum(x * x));
    float n1 = fmaxf(raw, EPSF);
    float f = tanhf(0.1f * n1) / (0.1f * n1);
    float a = f * x;
    float na = f * raw;
    float nac = fmaxf(na, EPSF);
    float ps = (nac > MAXNORM()) ? MAXNORM() / nac : 1.f;
    a *= ps;
    if (lane < 16) g_ne[wid * 16 + lane] = a;
    if (lane == 0) g_nen[wid] = fmaxf(na * ps, EPSF);
}

// ---------------- quad mobius tail; thread owns outs j = q*16 + sub*4 + c (idx q*4+c) ----------------
// hq = sH + hoff + sub*4 ; element for idx (q*4+c) is hq[q*16+c].
__device__ __forceinline__ void tail_q(const float* m, float xn, float at1,
                                       const float* hq, float y2,
                                       float* z, float& n_out) {
    float s2 = 0.f, amax = 0.f;
#pragma unroll
    for (int j = 0; j < 16; j++) { s2 = fmaf(m[j], m[j], s2); amax = fmaxf(amax, fabsf(m[j])); }
    s2 = qsum(s2);
    amax = qmax(amax);
    float mxn_raw = sqrtf(s2);
    float mxn = fmaxf(mxn_raw, EPSF);
    float th = tanhf(mxn / xn * at1);
    float sc = 10.f * th / mxn;
    float nr = sc * mxn_raw;
    if (amax == 0.f) { sc = 0.f; nr = 0.f; }
    float nrc = fmaxf(nr, EPSF);
    float ps = (nrc > MAXNORM()) ? MAXNORM() / nrc : 1.f;
    float f1 = sc * ps;
    float nafter = nr * ps;
    float x2 = nafter * nafter;

    if (y2 > 0.f) {
        float xy = 0.f;
#pragma unroll
        for (int q = 0; q < 4; q++)
#pragma unroll
            for (int c = 0; c < 4; c++) {
                z[q * 4 + c] = f1 * m[q * 4 + c];
                xy = fmaf(z[q * 4 + c], hq[q * 16 + c], xy);
            }
        xy = qsum(xy);
        float c1 = 1.f + 0.02f * xy + 0.01f * y2;
        float c2 = 1.f - 0.01f * x2;
        float den = fmaxf(1.f + 0.02f * xy + 1e-4f * x2 * y2, EPSF);
        float nza = sqrtf(fmaxf(c1 * c1 * x2 + 2.f * c1 * c2 * xy + c2 * c2 * y2, 0.f)) / den;
        float nzc = fmaxf(nza, EPSF);
        float ps2 = (nzc > MAXNORM()) ? MAXNORM() / nzc : 1.f;
        float g1 = c1 / den * ps2, g2 = c2 / den * ps2;
#pragma unroll
        for (int q = 0; q < 4; q++)
#pragma unroll
            for (int c = 0; c < 4; c++)
                z[q * 4 + c] = fmaf(g1, z[q * 4 + c], g2 * hq[q * 16 + c]);
        n_out = fmaxf(nza * ps2, EPSF);
    } else {
#pragma unroll
        for (int j = 0; j < 16; j++) z[j] = f1 * m[j];
        n_out = fmaxf(nafter, EPSF);
    }
}

// ---------------- head MLP: fused 2-phase; 256 thr, 64 rows/block; phase2 = 1 row x 16 outs ----------------
constexpr int RB  = 64;    // rows per block
constexpr int TBH = 256;   // threads per block (64 quads)
constexpr int ZP  = 68;    // sZT row pitch (even, != 0 mod 32)

__global__ __launch_bounds__(TBH, 3) void k_head(const float* __restrict__ w1,
                                                 const float* __restrict__ w2,
                                                 float* __restrict__ out) {
    __shared__ __align__(16) float sW1T[16 * 64];   // [k][j]
    __shared__ __align__(16) float sW2T[64 * 64];   // [k][j]
    __shared__ __align__(16) float sZT[64 * ZP];    // [k][row]  (z transposed)
    __shared__ float sH[128];
    __shared__ float sXN2[RB];
    __shared__ float sY[2];
    int tid = threadIdx.x;
    for (int i = tid; i < 1024; i += TBH) { int j = i >> 4, k = i & 15; sW1T[k * 64 + j] = w1[i]; }
    for (int i = tid; i < 4096; i += TBH) { int j = i >> 6, k = i & 63; sW2T[k * 64 + j] = w2[i]; }
    for (int i = tid; i < 128; i += TBH) sH[i] = g_hb[i];
    __syncthreads();
    if (tid < 2) {
        float y = 0.f;
#pragma unroll
        for (int j = 0; j < 64; j++) { float h = sH[tid * 64 + j]; y = fmaf(h, h, y); }
        sY[tid] = y;
    }
    __syncthreads();

    int sub = tid & 3, rg = tid >> 2;          // rg 0..63  (quad id == local row)
    float y2a = sY[0], y2b = sY[1];
    int rbase = blockIdx.x * RB;

    // ---------- phase 1: quad-per-row 16->64 + SiLU + dropout -> sZT (single pass) ----------
    {
        int rl = rg;
        int r = min(rbase + rl, NG * NNODES - 1);   // clamp: no divergence around shuffles
        float4 xv = *(const float4*)(g_ne + r * 16 + sub * 4);
        float x4[4] = {xv.x, xv.y, xv.z, xv.w};
        float xn = g_nen[r];
        float at1 = atanhf(fminf(0.1f * xn, CLIPT));

        float m[16];
#pragma unroll
        for (int j = 0; j < 16; j++) m[j] = 0.f;
#pragma unroll
        for (int o = 0; o < 4; o++)
#pragma unroll
            for (int i = 0; i < 4; i++) {
                float xk = __shfl_sync(FULLMASK, x4[i], o, 4);
                const float4* wr = (const float4*)(sW1T + (4 * o + i) * 64 + sub * 4);
#pragma unroll
                for (int q = 0; q < 4; q++) {
                    float4 wv = wr[q * 4];
                    m[q * 4 + 0] = fmaf(wv.x, xk, m[q * 4 + 0]);
                    m[q * 4 + 1] = fmaf(wv.y, xk, m[q * 4 + 1]);
                    m[q * 4 + 2] = fmaf(wv.z, xk, m[q * 4 + 2]);
                    m[q * 4 + 3] = fmaf(wv.w, xk, m[q * 4 + 3]);
                }
            }
        float z[16], nz1;
        tail_q(m, xn, at1, sH + sub * 4, y2a, z, nz1);

        // SiLU act
        float nact;
        {
            float t = fminf(0.1f * nz1, CLIPT);
            float lf = atanhf(t) / (0.1f * nz1);
            float s2 = 0.f;
#pragma unroll
            for (int j = 0; j < 16; j++) {
                float u = lf * z[j];
                u = u / (1.f + __expf(-u));
                z[j] = u;
                s2 = fmaf(u, u, s2);
            }
            s2 = qsum(s2);
            float n2r = sqrtf(s2);
            float n2 = fmaxf(n2r, EPSF);
            float ef = tanhf(0.1f * n2) / (0.1f * n2);
            float na = ef * n2r;
            float nac = fmaxf(na, EPSF);
            float ps = (nac > MAXNORM()) ? MAXNORM() / nac : 1.f;
            float s = ef * ps;
#pragma unroll
            for (int j = 0; j < 16; j++) z[j] *= s;
            nact = fmaxf(na * ps, EPSF);
        }
        // HypDropout (eval): scalar chain
        float xn2;
        {
            float t = fminf(0.1f * nact, CLIPT);
            float lf = atanhf(t) / (0.1f * nact);
            float nu = lf * nact;
            float nuc = fmaxf(nu, EPSF);
            float ef = tanhf(0.1f * nuc) / (0.1f * nuc);
            float nd = ef * nu;
            float ndc = fmaxf(nd, EPSF);
            float ps = (ndc > MAXNORM()) ? MAXNORM() / ndc : 1.f;
            float s = lf * ef * ps;
#pragma unroll
            for (int j = 0; j < 16; j++) z[j] *= s;
            xn2 = fmaxf(nd * ps, EPSF);
        }
        // stage z transposed + xn2
#pragma unroll
        for (int q = 0; q < 4; q++)
#pragma unroll
            for (int c = 0; c < 4; c++)
                sZT[(q * 16 + sub * 4 + c) * ZP + rl] = z[q * 4 + c];
        if (sub == 0) sXN2[rl] = xn2;
    }
    __syncthreads();

    // ---------- phase 2: register-tiled 64->64 (1 row x 16 outs per thread) ----------
    float acc[16];
#pragma unroll
    for (int j = 0; j < 16; j++) acc[j] = 0.f;

#pragma unroll 4
    for (int k = 0; k < 64; k++) {
        float zk = sZT[k * ZP + rg];                            // broadcast within quad
        const float4* wr = (const float4*)(sW2T + k * 64 + sub * 4);
        float4 wa = wr[0], wb = wr[4], wc = wr[8], wd = wr[12];
        acc[0]  = fmaf(wa.x, zk, acc[0]);  acc[1]  = fmaf(wa.y, zk, acc[1]);
        acc[2]  = fmaf(wa.z, zk, acc[2]);  acc[3]  = fmaf(wa.w, zk, acc[3]);
        acc[4]  = fmaf(wb.x, zk, acc[4]);  acc[5]  = fmaf(wb.y, zk, acc[5]);
        acc[6]  = fmaf(wb.z, zk, acc[6]);  acc[7]  = fmaf(wb.w, zk, acc[7]);
        acc[8]  = fmaf(wc.x, zk, acc[8]);  acc[9]  = fmaf(wc.y, zk, acc[9]);
        acc[10] = fmaf(wc.z, zk, acc[10]); acc[11] = fmaf(wc.w, zk, acc[11]);
        acc[12] = fmaf(wd.x, zk, acc[12]); acc[13] = fmaf(wd.y, zk, acc[13]);
        acc[14] = fmaf(wd.z, zk, acc[14]); acc[15] = fmaf(wd.w, zk, acc[15]);
    }

    {
        int rglob = rbase + rg;
        float xn2 = sXN2[rg];
        float at2 = atanhf(fminf(0.1f * xn2, CLIPT));
        float o16[16], nout;
        tail_q(acc, xn2, at2, sH + 64 + sub * 4, y2b, o16, nout);
        if (rglob < NG * NNODES) {
#pragma unroll
            for (int q = 0; q < 4; q++) {
                float4 v;
                v.x = o16[q * 4 + 0]; v.y = o16[q * 4 + 1];
                v.z = o16[q * 4 + 2]; v.w = o16[q * 4 + 3];
                *(float4*)(out + rglob * 64 + q * 16 + sub * 4) = v;
            }
        }
    }
}

// ---------------- launch ----------------
extern "C" void kernel_launch(void* const* d_in, const int* in_sizes, int n_in,
                              void* d_out, int out_size) {
    const int*   ei   = (const int*)d_in[1];
    const float* emb  = (const float*)d_in[2];
    const float* atti = (const float*)d_in[3];
    const float* attj = (const float*)d_in[4];
    const float* w1   = (const float*)d_in[5];
    const float* b1   = (const float*)d_in[6];
    const float* w2   = (const float*)d_in[7];
    const float* b2   = (const float*)d_in[8];
    float* out = (float*)d_out;

    k_prep<<<1251, 256>>>(emb, atti, attj, b1, b2);
    k_scatter<<<(NG * (NE / 4) + 255) / 256, 256>>>(ei);
    k_gather<<<(NG * NNODES + 7) / 8, 256>>>();
    k_head<<<(NG * NNODES + RB - 1) / RB, TBH>>>(w1, w2, out);
}

// round 16
// speedup vs baseline: 1.0077x; 1.0077x over previous
#include <cuda_runtime.h>
#include <math.h>

// ---------------- problem constants ----------------
constexpr int NNODES = 10000;
constexpr int HDIM   = 64;
constexpr int NHEADS = 4;
constexpr int OCDIM  = 16;
constexpr int NE     = 160000;
constexpr int NG     = 2;             // only graphs 3 and 7 are used
constexpr int CAP    = 128;           // per-node edge-list capacity (deg ~ Poisson(16))

#define FULLMASK 0xffffffffu
__device__ __forceinline__ float MAXNORM() { return 9.96f; }  // (1-4e-3)/0.1
#define EPSF   1e-15f
#define CLIPT  (1.0f - 1e-7f)

// ---------------- scratch (no allocations allowed) ----------------
__device__ __align__(16) float    g_xt[NNODES * HDIM];
__device__ __align__(16) float    g_ai[NNODES * NHEADS];
__device__ __align__(16) float    g_aj[NNODES * NHEADS];
__device__               int      g_cnt[NG * NNODES];
__device__ __align__(16) int      g_edst[NG * NNODES * CAP];
__device__ __align__(16) float    g_eexp[NG * NNODES * CAP * 4];  // per-edge exp weights
__device__ __align__(16) float    g_ne[NG * NNODES * OCDIM];
__device__               float    g_nen[NG * NNODES];    // ‖g_ne row‖ (>=EPS)
__device__               float    g_hb[2 * HDIM];

// ---------------- helpers ----------------
__device__ __forceinline__ float wsum(float v) {
#pragma unroll
    for (int o = 16; o; o >>= 1) v += __shfl_xor_sync(FULLMASK, v, o);
    return v;
}
__device__ __forceinline__ float qsum(float v) {
    v += __shfl_xor_sync(FULLMASK, v, 1, 4);
    v += __shfl_xor_sync(FULLMASK, v, 2, 4);
    return v;
}
__device__ __forceinline__ float qmax(float v) {
    v = fmaxf(v, __shfl_xor_sync(FULLMASK, v, 1, 4));
    v = fmaxf(v, __shfl_xor_sync(FULLMASK, v, 2, 4));
    return v;
}
__device__ __forceinline__ float4 edge_exp(float4 ai, float4 aj) {
    float a0 = ai.x + aj.x; a0 = a0 >= 0.f ? a0 : 0.2f * a0;
    float a1 = ai.y + aj.y; a1 = a1 >= 0.f ? a1 : 0.2f * a1;
    float a2 = ai.z + aj.z; a2 = a2 >= 0.f ? a2 : 0.2f * a2;
    float a3 = ai.w + aj.w; a3 = a3 >= 0.f ? a3 : 0.2f * a3;
    float4 ev;
    ev.x = __expf(a0); ev.y = __expf(a1); ev.z = __expf(a2); ev.w = __expf(a3);
    return ev;
}

// ---------------- fused prep: zero counters + per-node xt/att dots + hb ----------------
__global__ void k_prep(const float* __restrict__ emb,
                       const float* __restrict__ atti,
                       const float* __restrict__ attj,
                       const float* __restrict__ b1,
                       const float* __restrict__ b2) {
    int gid = blockIdx.x * blockDim.x + threadIdx.x;
    if (gid < NG * NNODES) g_cnt[gid] = 0;

    int w = threadIdx.x >> 5, lane = threadIdx.x & 31;

    if (blockIdx.x == 1250) {
        if (w < 2) {
            const float* b = w ? b2 : b1;
            float u0 = b[lane], u1 = b[lane + 32];
            float raw = sqrtf(wsum(u0 * u0 + u1 * u1));
            float n1 = fmaxf(raw, EPSF);
            float f = tanhf(0.1f * n1) / (0.1f * n1);
            float a = f * u0, c = f * u1;
            float na = f * raw;
            float nac = fmaxf(na, EPSF);
            if (nac > MAXNORM()) { float s = MAXNORM() / nac; a *= s; c *= s; }
            g_hb[w * 64 + lane] = a;
            g_hb[w * 64 + lane + 32] = c;
        }
        return;
    }

    __shared__ float sx[8][64];
    int n = blockIdx.x * 8 + w;
    if (n >= NNODES) return;
    const float* er = emb + n * 64;
    float u0 = er[lane], u1 = er[lane + 32];
    float raw = sqrtf(wsum(u0 * u0 + u1 * u1));
    float n1 = fmaxf(raw, EPSF);
    float f = tanhf(0.1f * n1) / (0.1f * n1);
    float a = f * u0, b = f * u1;
    float na = f * raw;
    float nac = fmaxf(na, EPSF);
    float ps = (nac > MAXNORM()) ? MAXNORM() / nac : 1.f;
    a *= ps; b *= ps;
    float n3 = fmaxf(na * ps, EPSF);
    float t = fminf(0.1f * n3, CLIPT);
    float lf = atanhf(t) / (0.1f * n3);
    a *= lf; b *= lf;
    g_xt[n * 64 + lane] = a;
    g_xt[n * 64 + lane + 32] = b;
    sx[w][lane] = a; sx[w][lane + 32] = b;
    __syncwarp();
    if (lane < 8) {
        int h = lane & 3;
        const float* att = (lane < 4) ? atti : attj;
        float s = 0.f;
#pragma unroll
        for (int k = 0; k < 16; k++) s += sx[w][h * 16 + k] * att[h * 16 + k];
        if (lane < 4) g_ai[n * 4 + h] = s; else g_aj[n * 4 + h] = s;
    }
}

// ---------------- bin edges by src (CSR) + precompute edge exp weights ----------------
__global__ void k_scatter(const int* __restrict__ ei) {
    constexpr int Q = NE / 4;
    int t = blockIdx.x * blockDim.x + threadIdx.x;
    if (t >= NG * Q) return;
    int gi = t / Q, q = t - gi * Q;
    int g = 3 + 4 * gi;
    const int4 s4 = ((const int4*)(ei + (size_t)g * 2 * NE))[q];
    const int4 d4 = ((const int4*)(ei + (size_t)g * 2 * NE + NE))[q];
    int nb = gi * NNODES;
    int p0 = atomicAdd(&g_cnt[nb + s4.x], 1);
    int p1 = atomicAdd(&g_cnt[nb + s4.y], 1);
    int p2 = atomicAdd(&g_cnt[nb + s4.z], 1);
    int p3 = atomicAdd(&g_cnt[nb + s4.w], 1);
    float4 ai0 = *(const float4*)(g_ai + s4.x * 4);
    float4 ai1 = *(const float4*)(g_ai + s4.y * 4);
    float4 ai2 = *(const float4*)(g_ai + s4.z * 4);
    float4 ai3 = *(const float4*)(g_ai + s4.w * 4);
    float4 aj0 = *(const float4*)(g_aj + d4.x * 4);
    float4 aj1 = *(const float4*)(g_aj + d4.y * 4);
    float4 aj2 = *(const float4*)(g_aj + d4.z * 4);
    float4 aj3 = *(const float4*)(g_aj + d4.w * 4);
    if (p0 < CAP) {
        g_edst[(nb + s4.x) * CAP + p0] = d4.x;
        *(float4*)(g_eexp + ((nb + s4.x) * CAP + p0) * 4) = edge_exp(ai0, aj0);
    }
    if (p1 < CAP) {
        g_edst[(nb + s4.y) * CAP + p1] = d4.y;
        *(float4*)(g_eexp + ((nb + s4.y) * CAP + p1) * 4) = edge_exp(ai1, aj1);
    }
    if (p2 < CAP) {
        g_edst[(nb + s4.z) * CAP + p2] = d4.z;
        *(float4*)(g_eexp + ((nb + s4.z) * CAP + p2) * 4) = edge_exp(ai2, aj2);
    }
    if (p3 < CAP) {
        g_edst[(nb + s4.w) * CAP + p3] = d4.w;
        *(float4*)(g_eexp + ((nb + s4.w) * CAP + p3) * 4) = edge_exp(ai3, aj3);
    }
}

// ---------------- per-node gather: coalesced exp-weight load + tight FMA phase ----------------
__global__ void k_gather() {
    __shared__ float sE[8][32 * 4];
    __shared__ int   sD[8][32];
    int w = threadIdx.x >> 5, lane = threadIdx.x & 31;
    int wid = blockIdx.x * 8 + w;
    if (wid >= NG * NNODES) return;
    int gi = wid / NNODES, nsrc = wid - gi * NNODES;

    int h1 = lane >> 4, h2 = h1 + 2;

    int deg = min(g_cnt[gi * NNODES + nsrc], CAP);
    const int*   lst = g_edst + (gi * NNODES + nsrc) * CAP;
    const float* ewp = g_eexp + (size_t)(gi * NNODES + nsrc) * CAP * 4;
    int total = deg + 1;   // + self loop

    // self-loop weight (same for all lanes)
    float4 ai4 = *(const float4*)(g_ai + nsrc * 4);
    float4 ajs = *(const float4*)(g_aj + nsrc * 4);
    float4 evself = edge_exp(ai4, ajs);

    float acc1 = 0.f, acc2 = 0.f;
    float s0 = 0.f, s1a = 0.f, s2a = 0.f, s3a = 0.f;

    for (int base = 0; base < total; base += 32) {
        int idx = base + lane;
        int dl = nsrc;
        float4 ev = {0.f, 0.f, 0.f, 0.f};
        if (idx < deg) {
            dl = lst[idx];
            ev = *(const float4*)(ewp + idx * 4);
        } else if (idx == deg) {
            ev = evself;
        }
        s0 += ev.x; s1a += ev.y; s2a += ev.z; s3a += ev.w;
        sD[w][lane] = dl;
        *(float4*)(&sE[w][lane * 4]) = ev;
        __syncwarp();
        int m = min(32, total - base);
#pragma unroll 4
        for (int j = 0; j < m; j++) {
            int d = sD[w][j];
            float e1 = sE[w][j * 4 + h1];
            float e2 = sE[w][j * 4 + h2];
            acc1 = fmaf(e1, g_xt[d * 64 + lane], acc1);
            acc2 = fmaf(e2, g_xt[d * 64 + lane + 32], acc2);
        }
        __syncwarp();
    }
    s0 = wsum(s0); s1a = wsum(s1a); s2a = wsum(s2a); s3a = wsum(s3a);
    float sh1 = h1 ? s1a : s0;
    float sh2 = h1 ? s3a : s2a;
    float v = acc1 / sh1 + acc2 / sh2;
    v += __shfl_xor_sync(FULLMASK, v, 16);
    float x = (lane < 16) ? v * 0.25f : 0.f;

    float raw = sqrtf(wsum(x * x));
    float n1 = fmaxf(raw, EPSF);
    float f = tanhf(0.1f * n1) / (0.1f * n1);
    float a = f * x;
    float na = f * raw;
    float nac = fmaxf(na, EPSF);
    float ps = (nac > MAXNORM()) ? MAXNORM() / nac : 1.f;
    a *= ps;
    if (lane < 16) g_ne[wid * 16 + lane] = a;
    if (lane == 0) g_nen[wid] = fmaxf(na * ps, EPSF);
}

// ---------------- quad mobius tail; thread owns outs j = q*16 + sub*4 + c (idx q*4+c) ----------------
// hq = sH + hoff + sub*4 ; element for idx (q*4+c) is hq[q*16+c].
__device__ __forceinline__ void tail_q(const float* m, float xn, float at1,
                                       const float* hq, float y2,
                                       float* z, float& n_out) {
    float s2 = 0.f, amax = 0.f;
#pragma unroll
    for (int j = 0; j < 16; j++) { s2 = fmaf(m[j], m[j], s2); amax = fmaxf(amax, fabsf(m[j])); }
    s2 = qsum(s2);
    amax = qmax(amax);
    float mxn_raw = sqrtf(s2);
    float mxn = fmaxf(mxn_raw, EPSF);
    float th = tanhf(mxn / xn * at1);
    float sc = 10.f * th / mxn;
    float nr = sc * mxn_raw;
    if (amax == 0.f) { sc = 0.f; nr = 0.f; }
    float nrc = fmaxf(nr, EPSF);
    float ps = (nrc > MAXNORM()) ? MAXNORM() / nrc : 1.f;
    float f1 = sc * ps;
    float nafter = nr * ps;
    float x2 = nafter * nafter;

    if (y2 > 0.f) {
        float xy = 0.f;
#pragma unroll
        for (int q = 0; q < 4; q++)
#pragma unroll
            for (int c = 0; c < 4; c++) {
                z[q * 4 + c] = f1 * m[q * 4 + c];
                xy = fmaf(z[q * 4 + c], hq[q * 16 + c], xy);
            }
        xy = qsum(xy);
        float c1 = 1.f + 0.02f * xy + 0.01f * y2;
        float c2 = 1.f - 0.01f * x2;
        float den = fmaxf(1.f + 0.02f * xy + 1e-4f * x2 * y2, EPSF);
        float nza = sqrtf(fmaxf(c1 * c1 * x2 + 2.f * c1 * c2 * xy + c2 * c2 * y2, 0.f)) / den;
        float nzc = fmaxf(nza, EPSF);
        float ps2 = (nzc > MAXNORM()) ? MAXNORM() / nzc : 1.f;
        float g1 = c1 / den * ps2, g2 = c2 / den * ps2;
#pragma unroll
        for (int q = 0; q < 4; q++)
#pragma unroll
            for (int c = 0; c < 4; c++)
                z[q * 4 + c] = fmaf(g1, z[q * 4 + c], g2 * hq[q * 16 + c]);
        n_out = fmaxf(nza * ps2, EPSF);
    } else {
#pragma unroll
        for (int j = 0; j < 16; j++) z[j] = f1 * m[j];
        n_out = fmaxf(nafter, EPSF);
    }
}

// ---------------- head MLP: fused 2-phase, register-tiled GEMM2 (2 rows x 16 outs / thread) ----------------
constexpr int RB  = 64;    // rows per block
constexpr int TBH = 128;   // threads per block (32 quads)
constexpr int ZP  = 68;    // sZT row pitch (even, != 0 mod 32)

__global__ __launch_bounds__(TBH, 4) void k_head(const float* __restrict__ w1,
                                                 const float* __restrict__ w2,
                                                 float* __restrict__ out) {
    __shared__ __align__(16) float sW1T[16 * 64];   // [k][j]
    __shared__ __align__(16) float sW2T[64 * 64];   // [k][j]
    __shared__ __align__(16) float sZT[64 * ZP];    // [k][row]  (z transposed)
    __shared__ float sH[128];
    __shared__ float sXN2[RB];
    __shared__ float sY[2];
    int tid = threadIdx.x;
    for (int i = tid; i < 1024; i += TBH) { int j = i >> 4, k = i & 15; sW1T[k * 64 + j] = w1[i]; }
    for (int i = tid; i < 4096; i += TBH) { int j = i >> 6, k = i & 63; sW2T[k * 64 + j] = w2[i]; }
    for (int i = tid; i < 128; i += TBH) sH[i] = g_hb[i];
    __syncthreads();
    if (tid < 2) {
        float y = 0.f;
#pragma unroll
        for (int j = 0; j < 64; j++) { float h = sH[tid * 64 + j]; y = fmaf(h, h, y); }
        sY[tid] = y;
    }
    __syncthreads();

    int sub = tid & 3, rg = tid >> 2;          // rg 0..31
    float y2a = sY[0], y2b = sY[1];
    int rbase = blockIdx.x * RB;

    // ---------- phase 1: quad-per-row 16->64 + SiLU + dropout -> sZT ----------
    // NOTE: deliberately NOT unrolled (unrolling doubles live state -> reg spill; R13 lesson)
    for (int pass = 0; pass < 2; pass++) {
        int rl = pass * 32 + rg;
        int r = min(rbase + rl, NG * NNODES - 1);   // clamp: no divergence around shuffles
        float4 xv = *(const float4*)(g_ne + r * 16 + sub * 4);
        float x4[4] = {xv.x, xv.y, xv.z, xv.w};
        float xn = g_nen[r];
        float at1 = atanhf(fminf(0.1f * xn, CLIPT));

        float m[16];
#pragma unroll
        for (int j = 0; j < 16; j++) m[j] = 0.f;
#pragma unroll
        for (int o = 0; o < 4; o++)
#pragma unroll
            for (int i = 0; i < 4; i++) {
                float xk = __shfl_sync(FULLMASK, x4[i], o, 4);
                const float4* wr = (const float4*)(sW1T + (4 * o + i) * 64 + sub * 4);
#pragma unroll
                for (int q = 0; q < 4; q++) {
                    float4 wv = wr[q * 4];
                    m[q * 4 + 0] = fmaf(wv.x, xk, m[q * 4 + 0]);
                    m[q * 4 + 1] = fmaf(wv.y, xk, m[q * 4 + 1]);
                    m[q * 4 + 2] = fmaf(wv.z, xk, m[q * 4 + 2]);
                    m[q * 4 + 3] = fmaf(wv.w, xk, m[q * 4 + 3]);
                }
            }
        float z[16], nz1;
        tail_q(m, xn, at1, sH + sub * 4, y2a, z, nz1);

        // SiLU act
        float nact;
        {
            float t = fminf(0.1f * nz1, CLIPT);
            float lf = atanhf(t) / (0.1f * nz1);
            float s2 = 0.f;
#pragma unroll
            for (int j = 0; j < 16; j++) {
                float u = lf * z[j];
                u = u / (1.f + __expf(-u));
                z[j] = u;
                s2 = fmaf(u, u, s2);
            }
            s2 = qsum(s2);
            float n2r = sqrtf(s2);
            float n2 = fmaxf(n2r, EPSF);
            float ef = tanhf(0.1f * n2) / (0.1f * n2);
            float na = ef * n2r;
            float nac = fmaxf(na, EPSF);
            float ps = (nac > MAXNORM()) ? MAXNORM() / nac : 1.f;
            float s = ef * ps;
#pragma unroll
            for (int j = 0; j < 16; j++) z[j] *= s;
            nact = fmaxf(na * ps, EPSF);
        }
        // HypDropout (eval): scalar chain
        float xn2;
        {
            float t = fminf(0.1f * nact, CLIPT);
            float lf = atanhf(t) / (0.1f * nact);
            float nu = lf * nact;
            float nuc = fmaxf(nu, EPSF);
            float ef = tanhf(0.1f * nuc) / (0.1f * nuc);
            float nd = ef * nu;
            float ndc = fmaxf(nd, EPSF);
            float ps = (ndc > MAXNORM()) ? MAXNORM() / ndc : 1.f;
            float s = lf * ef * ps;
#pragma unroll
            for (int j = 0; j < 16; j++) z[j] *= s;
            xn2 = fmaxf(nd * ps, EPSF);
        }
        // stage z transposed + xn2
#pragma unroll
        for (int q = 0; q < 4; q++)
#pragma unroll
            for (int c = 0; c < 4; c++)
                sZT[(q * 16 + sub * 4 + c) * ZP + rl] = z[q * 4 + c];
        if (sub == 0) sXN2[rl] = xn2;
    }
    __syncthreads();

    // ---------- phase 2: register-tiled 64->64 (2 rows x 16 outs per thread) ----------
    float acc[2][16];
#pragma unroll
    for (int i = 0; i < 2; i++)
#pragma unroll
        for (int j = 0; j < 16; j++) acc[i][j] = 0.f;

#pragma unroll 4
    for (int k = 0; k < 64; k++) {
        float2 zr = *(const float2*)(sZT + k * ZP + rg * 2);   // z_k for my 2 rows
        const float4* wr = (const float4*)(sW2T + k * 64 + sub * 4);
        float4 wa = wr[0], wb = wr[4], wc = wr[8], wd = wr[12];
        float wv[16] = {wa.x, wa.y, wa.z, wa.w, wb.x, wb.y, wb.z, wb.w,
                        wc.x, wc.y, wc.z, wc.w, wd.x, wd.y, wd.z, wd.w};
        float zk[2] = {zr.x, zr.y};
#pragma unroll
        for (int i = 0; i < 2; i++)
#pragma unroll
            for (int j = 0; j < 16; j++)
                acc[i][j] = fmaf(wv[j], zk[i], acc[i][j]);
    }

#pragma unroll
    for (int i = 0; i < 2; i++) {
        int rl = rg * 2 + i;
        int rglob = rbase + rl;
        float xn2 = sXN2[rl];
        float at2 = atanhf(fminf(0.1f * xn2, CLIPT));
        float o16[16], nout;
        tail_q(acc[i], xn2, at2, sH + 64 + sub * 4, y2b, o16, nout);
        if (rglob < NG * NNODES) {
#pragma unroll
            for (int q = 0; q < 4; q++) {
                float4 v;
                v.x = o16[q * 4 + 0]; v.y = o16[q * 4 + 1];
                v.z = o16[q * 4 + 2]; v.w = o16[q * 4 + 3];
                *(float4*)(out + rglob * 64 + q * 16 + sub * 4) = v;
            }
        }
    }
}

// ---------------- launch ----------------
extern "C" void kernel_launch(void* const* d_in, const int* in_sizes, int n_in,
                              void* d_out, int out_size) {
    const int*   ei   = (const int*)d_in[1];
    const float* emb  = (const float*)d_in[2];
    const float* atti = (const float*)d_in[3];
    const float* attj = (const float*)d_in[4];
    const float* w1   = (const float*)d_in[5];
    const float* b1   = (const float*)d_in[6];
    const float* w2   = (const float*)d_in[7];
    const float* b2   = (const float*)d_in[8];
    float* out = (float*)d_out;

    k_prep<<<1251, 256>>>(emb, atti, attj, b1, b2);
    k_scatter<<<(NG * (NE / 4) + 255) / 256, 256>>>(ei);
    k_gather<<<(NG * NNODES + 7) / 8, 256>>>();
    k_head<<<(NG * NNODES + RB - 1) / RB, TBH>>>(w1, w2, out);
}

// round 17
// speedup vs baseline: 1.0453x; 1.0373x over previous
#include <cuda_runtime.h>
#include <math.h>

// ---------------- problem constants ----------------
constexpr int NNODES = 10000;
constexpr int HDIM   = 64;
constexpr int NHEADS = 4;
constexpr int OCDIM  = 16;
constexpr int NE     = 160000;
constexpr int NG     = 2;             // only graphs 3 and 7 are used
constexpr int CAP    = 128;           // per-node edge-list capacity (deg ~ Poisson(16))

#define FULLMASK 0xffffffffu
__device__ __forceinline__ float MAXNORM() { return 9.96f; }  // (1-4e-3)/0.1
#define EPSF   1e-15f
#define CLIPT  (1.0f - 1e-7f)

// ---------------- fast transcendentals (HW tanh, log-based atanh) ----------------
__device__ __forceinline__ float fast_tanh(float x) {
    float y;
    asm("tanh.approx.f32 %0, %1;" : "=f"(y) : "f"(x));
    return y;
}
__device__ __forceinline__ float fast_atanh(float x) {
    return 0.5f * __logf(__fdividef(1.f + x, 1.f - x));
}

// ---------------- scratch (no allocations allowed) ----------------
__device__ __align__(16) float    g_xt[NNODES * HDIM];
__device__ __align__(16) float    g_ai[NNODES * NHEADS];
__device__ __align__(16) float    g_aj[NNODES * NHEADS];
__device__               int      g_cnt[NG * NNODES];
__device__ __align__(16) int      g_edst[NG * NNODES * CAP];
__device__ __align__(16) float    g_ne[NG * NNODES * OCDIM];
__device__               float    g_nen[NG * NNODES];    // ‖g_ne row‖ (>=EPS)
__device__               float    g_hb[2 * HDIM];

// ---------------- helpers ----------------
__device__ __forceinline__ float wsum(float v) {
#pragma unroll
    for (int o = 16; o; o >>= 1) v += __shfl_xor_sync(FULLMASK, v, o);
    return v;
}
__device__ __forceinline__ float qsum(float v) {
    v += __shfl_xor_sync(FULLMASK, v, 1, 4);
    v += __shfl_xor_sync(FULLMASK, v, 2, 4);
    return v;
}
__device__ __forceinline__ float qmax(float v) {
    v = fmaxf(v, __shfl_xor_sync(FULLMASK, v, 1, 4));
    v = fmaxf(v, __shfl_xor_sync(FULLMASK, v, 2, 4));
    return v;
}

// ---------------- fused prep: zero counters + per-node xt/att dots + hb ----------------
__global__ void k_prep(const float* __restrict__ emb,
                       const float* __restrict__ atti,
                       const float* __restrict__ attj,
                       const float* __restrict__ b1,
                       const float* __restrict__ b2) {
    int gid = blockIdx.x * blockDim.x + threadIdx.x;
    if (gid < NG * NNODES) g_cnt[gid] = 0;

    int w = threadIdx.x >> 5, lane = threadIdx.x & 31;

    if (blockIdx.x == 1250) {
        if (w < 2) {
            const float* b = w ? b2 : b1;
            float u0 = b[lane], u1 = b[lane + 32];
            float raw = sqrtf(wsum(u0 * u0 + u1 * u1));
            float n1 = fmaxf(raw, EPSF);
            float f = fast_tanh(0.1f * n1) / (0.1f * n1);
            float a = f * u0, c = f * u1;
            float na = f * raw;
            float nac = fmaxf(na, EPSF);
            if (nac > MAXNORM()) { float s = MAXNORM() / nac; a *= s; c *= s; }
            g_hb[w * 64 + lane] = a;
            g_hb[w * 64 + lane + 32] = c;
        }
        return;
    }

    __shared__ float sx[8][64];
    int n = blockIdx.x * 8 + w;
    if (n >= NNODES) return;
    const float* er = emb + n * 64;
    float u0 = er[lane], u1 = er[lane + 32];
    float raw = sqrtf(wsum(u0 * u0 + u1 * u1));
    float n1 = fmaxf(raw, EPSF);
    float f = fast_tanh(0.1f * n1) / (0.1f * n1);
    float a = f * u0, b = f * u1;
    float na = f * raw;
    float nac = fmaxf(na, EPSF);
    float ps = (nac > MAXNORM()) ? MAXNORM() / nac : 1.f;
    a *= ps; b *= ps;
    float n3 = fmaxf(na * ps, EPSF);
    float t = fminf(0.1f * n3, CLIPT);
    float lf = fast_atanh(t) / (0.1f * n3);
    a *= lf; b *= lf;
    g_xt[n * 64 + lane] = a;
    g_xt[n * 64 + lane + 32] = b;
    sx[w][lane] = a; sx[w][lane + 32] = b;
    __syncwarp();
    if (lane < 8) {
        int h = lane & 3;
        const float* att = (lane < 4) ? atti : attj;
        float s = 0.f;
#pragma unroll
        for (int k = 0; k < 16; k++) s += sx[w][h * 16 + k] * att[h * 16 + k];
        if (lane < 4) g_ai[n * 4 + h] = s; else g_aj[n * 4 + h] = s;
    }
}

// ---------------- bin edges by src (CSR, 4 edges per thread for MLP) ----------------
__global__ void k_scatter(const int* __restrict__ ei) {
    constexpr int Q = NE / 4;
    int t = blockIdx.x * blockDim.x + threadIdx.x;
    if (t >= NG * Q) return;
    int gi = t / Q, q = t - gi * Q;
    int g = 3 + 4 * gi;
    const int4 s4 = ((const int4*)(ei + (size_t)g * 2 * NE))[q];
    const int4 d4 = ((const int4*)(ei + (size_t)g * 2 * NE + NE))[q];
    int nb = gi * NNODES;
    int p0 = atomicAdd(&g_cnt[nb + s4.x], 1);
    int p1 = atomicAdd(&g_cnt[nb + s4.y], 1);
    int p2 = atomicAdd(&g_cnt[nb + s4.z], 1);
    int p3 = atomicAdd(&g_cnt[nb + s4.w], 1);
    if (p0 < CAP) g_edst[(nb + s4.x) * CAP + p0] = d4.x;
    if (p1 < CAP) g_edst[(nb + s4.y) * CAP + p1] = d4.y;
    if (p2 < CAP) g_edst[(nb + s4.z) * CAP + p2] = d4.z;
    if (p3 < CAP) g_edst[(nb + s4.w) * CAP + p3] = d4.w;
}

// ---------------- per-node gather: parallel exp phase + tight FMA phase ----------------
__global__ void k_gather() {
    __shared__ float sE[8][32 * 4];
    __shared__ int   sD[8][32];
    int w = threadIdx.x >> 5, lane = threadIdx.x & 31;
    int wid = blockIdx.x * 8 + w;
    if (wid >= NG * NNODES) return;
    int gi = wid / NNODES, nsrc = wid - gi * NNODES;

    float4 ai4 = *(const float4*)(g_ai + nsrc * 4);
    int h1 = lane >> 4, h2 = h1 + 2;

    int deg = min(g_cnt[gi * NNODES + nsrc], CAP);
    const int* lst = g_edst + (gi * NNODES + nsrc) * CAP;
    int total = deg + 1;   // + self loop

    float acc1 = 0.f, acc2 = 0.f;
    float s0 = 0.f, s1a = 0.f, s2a = 0.f, s3a = 0.f;

    for (int base = 0; base < total; base += 32) {
        int idx = base + lane;
        int dl = (idx < deg) ? lst[idx] : nsrc;
        float4 ev = {0.f, 0.f, 0.f, 0.f};
        if (idx < total) {
            float4 aj = *(const float4*)(g_aj + dl * 4);
            float a0 = ai4.x + aj.x; a0 = a0 >= 0.f ? a0 : 0.2f * a0;
            float a1 = ai4.y + aj.y; a1 = a1 >= 0.f ? a1 : 0.2f * a1;
            float a2 = ai4.z + aj.z; a2 = a2 >= 0.f ? a2 : 0.2f * a2;
            float a3 = ai4.w + aj.w; a3 = a3 >= 0.f ? a3 : 0.2f * a3;
            ev.x = __expf(a0); ev.y = __expf(a1);
            ev.z = __expf(a2); ev.w = __expf(a3);
            s0 += ev.x; s1a += ev.y; s2a += ev.z; s3a += ev.w;
        }
        sD[w][lane] = dl;
        *(float4*)(&sE[w][lane * 4]) = ev;
        __syncwarp();
        int m = min(32, total - base);
#pragma unroll 4
        for (int j = 0; j < m; j++) {
            int d = sD[w][j];
            float e1 = sE[w][j * 4 + h1];
            float e2 = sE[w][j * 4 + h2];
            acc1 = fmaf(e1, g_xt[d * 64 + lane], acc1);
            acc2 = fmaf(e2, g_xt[d * 64 + lane + 32], acc2);
        }
        __syncwarp();
    }
    s0 = wsum(s0); s1a = wsum(s1a); s2a = wsum(s2a); s3a = wsum(s3a);
    float sh1 = h1 ? s1a : s0;
    float sh2 = h1 ? s3a : s2a;
    float v = acc1 / sh1 + acc2 / sh2;
    v += __shfl_xor_sync(FULLMASK, v, 16);
    float x = (lane < 16) ? v * 0.25f : 0.f;

    float raw = sqrtf(wsum(x * x));
    float n1 = fmaxf(raw, EPSF);
    float f = fast_tanh(0.1f * n1) / (0.1f * n1);
    float a = f * x;
    float na = f * raw;
    float nac = fmaxf(na, EPSF);
    float ps = (nac > MAXNORM()) ? MAXNORM() / nac : 1.f;
    a *= ps;
    if (lane < 16) g_ne[wid * 16 + lane] = a;
    if (lane == 0) g_nen[wid] = fmaxf(na * ps, EPSF);
}

// ---------------- quad mobius tail; thread owns outs j = q*16 + sub*4 + c (idx q*4+c) ----------------
// hq = sH + hoff + sub*4 ; element for idx (q*4+c) is hq[q*16+c].
__device__ __forceinline__ void tail_q(const float* m, float xn, float at1,
                                       const float* hq, float y2,
                                       float* z, float& n_out) {
    float s2 = 0.f, amax = 0.f;
#pragma unroll
    for (int j = 0; j < 16; j++) { s2 = fmaf(m[j], m[j], s2); amax = fmaxf(amax, fabsf(m[j])); }
    s2 = qsum(s2);
    amax = qmax(amax);
    float mxn_raw = sqrtf(s2);
    float mxn = fmaxf(mxn_raw, EPSF);
    float th = fast_tanh(mxn / xn * at1);
    float sc = 10.f * th / mxn;
    float nr = sc * mxn_raw;
    if (amax == 0.f) { sc = 0.f; nr = 0.f; }
    float nrc = fmaxf(nr, EPSF);
    float ps = (nrc > MAXNORM()) ? MAXNORM() / nrc : 1.f;
    float f1 = sc * ps;
    float nafter = nr * ps;
    float x2 = nafter * nafter;

    if (y2 > 0.f) {
        float xy = 0.f;
#pragma unroll
        for (int q = 0; q < 4; q++)
#pragma unroll
            for (int c = 0; c < 4; c++) {
                z[q * 4 + c] = f1 * m[q * 4 + c];
                xy = fmaf(z[q * 4 + c], hq[q * 16 + c], xy);
            }
        xy = qsum(xy);
        float c1 = 1.f + 0.02f * xy + 0.01f * y2;
        float c2 = 1.f - 0.01f * x2;
        float den = fmaxf(1.f + 0.02f * xy + 1e-4f * x2 * y2, EPSF);
        float nza = sqrtf(fmaxf(c1 * c1 * x2 + 2.f * c1 * c2 * xy + c2 * c2 * y2, 0.f)) / den;
        float nzc = fmaxf(nza, EPSF);
        float ps2 = (nzc > MAXNORM()) ? MAXNORM() / nzc : 1.f;
        float g1 = c1 / den * ps2, g2 = c2 / den * ps2;
#pragma unroll
        for (int q = 0; q < 4; q++)
#pragma unroll
            for (int c = 0; c < 4; c++)
                z[q * 4 + c] = fmaf(g1, z[q * 4 + c], g2 * hq[q * 16 + c]);
        n_out = fmaxf(nza * ps2, EPSF);
    } else {
#pragma unroll
        for (int j = 0; j < 16; j++) z[j] = f1 * m[j];
        n_out = fmaxf(nafter, EPSF);
    }
}

// ---------------- head MLP: fused 2-phase, register-tiled GEMM2 (2 rows x 16 outs / thread) ----------------
constexpr int RB  = 64;    // rows per block
constexpr int TBH = 128;   // threads per block (32 quads)
constexpr int ZP  = 68;    // sZT row pitch (even, != 0 mod 32)

__global__ __launch_bounds__(TBH, 4) void k_head(const float* __restrict__ w1,
                                                 const float* __restrict__ w2,
                                                 float* __restrict__ out) {
    __shared__ __align__(16) float sW1T[16 * 64];   // [k][j]
    __shared__ __align__(16) float sW2T[64 * 64];   // [k][j]
    __shared__ __align__(16) float sZT[64 * ZP];    // [k][row]  (z transposed)
    __shared__ float sH[128];
    __shared__ float sXN2[RB];
    __shared__ float sY[2];
    int tid = threadIdx.x;
    for (int i = tid; i < 1024; i += TBH) { int j = i >> 4, k = i & 15; sW1T[k * 64 + j] = w1[i]; }
    for (int i = tid; i < 4096; i += TBH) { int j = i >> 6, k = i & 63; sW2T[k * 64 + j] = w2[i]; }
    for (int i = tid; i < 128; i += TBH) sH[i] = g_hb[i];
    __syncthreads();
    if (tid < 2) {
        float y = 0.f;
#pragma unroll
        for (int j = 0; j < 64; j++) { float h = sH[tid * 64 + j]; y = fmaf(h, h, y); }
        sY[tid] = y;
    }
    __syncthreads();

    int sub = tid & 3, rg = tid >> 2;          // rg 0..31
    float y2a = sY[0], y2b = sY[1];
    int rbase = blockIdx.x * RB;

    // ---------- phase 1: quad-per-row 16->64 + SiLU + dropout -> sZT ----------
    // NOTE: deliberately NOT unrolled (unrolling doubles live state -> reg spill; R13 lesson)
    for (int pass = 0; pass < 2; pass++) {
        int rl = pass * 32 + rg;
        int r = min(rbase + rl, NG * NNODES - 1);   // clamp: no divergence around shuffles
        float4 xv = *(const float4*)(g_ne + r * 16 + sub * 4);
        float x4[4] = {xv.x, xv.y, xv.z, xv.w};
        float xn = g_nen[r];
        float at1 = fast_atanh(fminf(0.1f * xn, CLIPT));

        float m[16];
#pragma unroll
        for (int j = 0; j < 16; j++) m[j] = 0.f;
#pragma unroll
        for (int o = 0; o < 4; o++)
#pragma unroll
            for (int i = 0; i < 4; i++) {
                float xk = __shfl_sync(FULLMASK, x4[i], o, 4);
                const float4* wr = (const float4*)(sW1T + (4 * o + i) * 64 + sub * 4);
#pragma unroll
                for (int q = 0; q < 4; q++) {
                    float4 wv = wr[q * 4];
                    m[q * 4 + 0] = fmaf(wv.x, xk, m[q * 4 + 0]);
                    m[q * 4 + 1] = fmaf(wv.y, xk, m[q * 4 + 1]);
                    m[q * 4 + 2] = fmaf(wv.z, xk, m[q * 4 + 2]);
                    m[q * 4 + 3] = fmaf(wv.w, xk, m[q * 4 + 3]);
                }
            }
        float z[16], nz1;
        tail_q(m, xn, at1, sH + sub * 4, y2a, z, nz1);

        // SiLU act
        float nact;
        {
            float t = fminf(0.1f * nz1, CLIPT);
            float lf = fast_atanh(t) / (0.1f * nz1);
            float s2 = 0.f;
#pragma unroll
            for (int j = 0; j < 16; j++) {
                float u = lf * z[j];
                u = u / (1.f + __expf(-u));
                z[j] = u;
                s2 = fmaf(u, u, s2);
            }
            s2 = qsum(s2);
            float n2r = sqrtf(s2);
            float n2 = fmaxf(n2r, EPSF);
            float ef = fast_tanh(0.1f * n2) / (0.1f * n2);
            float na = ef * n2r;
            float nac = fmaxf(na, EPSF);
            float ps = (nac > MAXNORM()) ? MAXNORM() / nac : 1.f;
            float s = ef * ps;
#pragma unroll
            for (int j = 0; j < 16; j++) z[j] *= s;
            nact = fmaxf(na * ps, EPSF);
        }
        // HypDropout (eval): scalar chain
        float xn2;
        {
            float t = fminf(0.1f * nact, CLIPT);
            float lf = fast_atanh(t) / (0.1f * nact);
            float nu = lf * nact;
            float nuc = fmaxf(nu, EPSF);
            float ef = fast_tanh(0.1f * nuc) / (0.1f * nuc);
            float nd = ef * nu;
            float ndc = fmaxf(nd, EPSF);
            float ps = (ndc > MAXNORM()) ? MAXNORM() / ndc : 1.f;
            float s = lf * ef * ps;
#pragma unroll
            for (int j = 0; j < 16; j++) z[j] *= s;
            xn2 = fmaxf(nd * ps, EPSF);
        }
        // stage z transposed + xn2
#pragma unroll
        for (int q = 0; q < 4; q++)
#pragma unroll
            for (int c = 0; c < 4; c++)
                sZT[(q * 16 + sub * 4 + c) * ZP + rl] = z[q * 4 + c];
        if (sub == 0) sXN2[rl] = xn2;
    }
    __syncthreads();

    // ---------- phase 2: register-tiled 64->64 (2 rows x 16 outs per thread) ----------
    float acc[2][16];
#pragma unroll
    for (int i = 0; i < 2; i++)
#pragma unroll
        for (int j = 0; j < 16; j++) acc[i][j] = 0.f;

#pragma unroll 4
    for (int k = 0; k < 64; k++) {
        float2 zr = *(const float2*)(sZT + k * ZP + rg * 2);   // z_k for my 2 rows
        const float4* wr = (const float4*)(sW2T + k * 64 + sub * 4);
        float4 wa = wr[0], wb = wr[4], wc = wr[8], wd = wr[12];
        float wv[16] = {wa.x, wa.y, wa.z, wa.w, wb.x, wb.y, wb.z, wb.w,
                        wc.x, wc.y, wc.z, wc.w, wd.x, wd.y, wd.z, wd.w};
        float zk[2] = {zr.x, zr.y};
#pragma unroll
        for (int i = 0; i < 2; i++)
#pragma unroll
            for (int j = 0; j < 16; j++)
                acc[i][j] = fmaf(wv[j], zk[i], acc[i][j]);
    }

#pragma unroll
    for (int i = 0; i < 2; i++) {
        int rl = rg * 2 + i;
        int rglob = rbase + rl;
        float xn2 = sXN2[rl];
        float at2 = fast_atanh(fminf(0.1f * xn2, CLIPT));
        float o16[16], nout;
        tail_q(acc[i], xn2, at2, sH + 64 + sub * 4, y2b, o16, nout);
        if (rglob < NG * NNODES) {
#pragma unroll
            for (int q = 0; q < 4; q++) {
                float4 v;
                v.x = o16[q * 4 + 0]; v.y = o16[q * 4 + 1];
                v.z = o16[q * 4 + 2]; v.w = o16[q * 4 + 3];
                *(float4*)(out + rglob * 64 + q * 16 + sub * 4) = v;
            }
        }
    }
}

// ---------------- launch ----------------
extern "C" void kernel_launch(void* const* d_in, const int* in_sizes, int n_in,
                              void* d_out, int out_size) {
    const int*   ei   = (const int*)d_in[1];
    const float* emb  = (const float*)d_in[2];
    const float* atti = (const float*)d_in[3];
    const float* attj = (const float*)d_in[4];
    const float* w1   = (const float*)d_in[5];
    const float* b1   = (const float*)d_in[6];
    const float* w2   = (const float*)d_in[7];
    const float* b2   = (const float*)d_in[8];
    float* out = (float*)d_out;

    k_prep<<<1251, 256>>>(emb, atti, attj, b1, b2);
    k_scatter<<<(NG * (NE / 4) + 255) / 256, 256>>>(ei);
    k_gather<<<(NG * NNODES + 7) / 8, 256>>>();
    k_head<<<(NG * NNODES + RB - 1) / RB, TBH>>>(w1, w2, out);
}